// round 5
// baseline (speedup 1.0000x reference)
#include <cuda_runtime.h>
#include <cstdint>

// Problem constants
#define B_  64
#define H_  128
#define W_  128
#define C_  10
#define FD_ 32
#define HID_ 64

// Tile config
#define TW 32
#define TH 8
#define HW 34   // halo width  (TW+2)
#define HH 10   // halo height (TH+2)
#define NPIX  (TW*TH)   // 256
#define NHALO (HW*HH)   // 340
#define NTHREADS 1024

// Shared memory layout (float offsets). Regions reused across phases:
//   SOUT aliases SY  (SY dead after phase C)
//   SAGG aliases SC  (SC dead after phase C)
//   SU   aliases SHS (SHS dead after phase D)
#define OFF_SY     0                          // NHALO*64 = 21760
#define OFF_SOUT   OFF_SY
#define OFF_SB     (OFF_SY + NHALO*HID_)      // rows padded to 12
#define OFF_SC     (OFF_SB + NHALO*12)        // NPIX*24
#define OFF_SAGG   OFF_SC                     // NPIX*12
#define OFF_SHS    (OFF_SC + NPIX*24)         // NPIX*64
#define OFF_SU     OFF_SHS
#define OFF_WSELF  (OFF_SHS + NPIX*HID_)
#define OFF_WNEIGH (OFF_WSELF + 640)
#define OFF_WC     (OFF_WNEIGH + 640)
#define OFF_MW2T   (OFF_WC + 192)
#define OFF_UW2T   (OFF_MW2T + 640)
#define OFF_UW1    (OFF_UW2T + 640)
#define OFF_UB1    (OFF_UW1 + 1280)
#define OFF_BASE   (OFF_UB1 + 64)
#define OFF_MB2    (OFF_BASE + 64)
#define OFF_UB2    (OFF_MB2 + 12)
#define OFF_GAMMA  (OFF_UB2 + 12)
#define OFF_BETA   (OFF_GAMMA + 12)
#define SMEM_FLOATS (OFF_BETA + 12)
#define SMEM_BYTES  (SMEM_FLOATS * 4)         // 210496

__global__ void __launch_bounds__(NTHREADS, 1)
cmp_kernel(const float* __restrict__ beliefs,
           const float* __restrict__ constraints,
           const float* __restrict__ fnembed,
           const float* __restrict__ mw1, const float* __restrict__ mb1,
           const float* __restrict__ mw2, const float* __restrict__ mb2,
           const float* __restrict__ uw1, const float* __restrict__ ub1,
           const float* __restrict__ uw2, const float* __restrict__ ub2,
           const float* __restrict__ gamma_, const float* __restrict__ beta_,
           float* __restrict__ out)
{
    extern __shared__ __align__(16) float sm[];
    const int tid = threadIdx.x;
    const int b  = blockIdx.z;
    const int x0 = blockIdx.x * TW;
    const int y0 = blockIdx.y * TH;

    // ================= Phase A: stage weights + inputs into smem =================
    // mw1 rows: [0,10)=W_self, [10,20)=W_neigh, [20,23)=W_con, [23,55)=W_fn
    for (int i = tid; i < 640; i += NTHREADS) {
        sm[OFF_WSELF  + i] = mw1[i];
        sm[OFF_WNEIGH + i] = mw1[640 + i];
        sm[OFF_MW2T + i] = mw2[(i & 63) * 10 + (i >> 6)];   // [k][j]
        sm[OFF_UW2T + i] = uw2[(i & 63) * 10 + (i >> 6)];
    }
    for (int i = tid; i < 192; i += NTHREADS)  sm[OFF_WC  + i] = mw1[1280 + i];
    for (int i = tid; i < 1280; i += NTHREADS) sm[OFF_UW1 + i] = uw1[i];
    if (tid < 64) {
        sm[OFF_UB1 + tid] = ub1[tid];
        float s = mb1[tid];
        const float* f = fnembed + b * FD_;
        #pragma unroll
        for (int k = 0; k < FD_; ++k)
            s = fmaf(f[k], mw1[(23 + k) * HID_ + tid], s);
        sm[OFF_BASE + tid] = s;
    }
    if (tid >= 64 && tid < 74) {
        int k = tid - 64;
        sm[OFF_MB2   + k] = mb2[k];
        sm[OFF_UB2   + k] = ub2[k];
        sm[OFF_GAMMA + k] = gamma_[k];
        sm[OFF_BETA  + k] = beta_[k];
    }

    // beliefs halo (replicate-pad), rows padded to 12 floats
    for (int idx = tid; idx < NHALO * C_; idx += NTHREADS) {
        int p = idx / C_, i = idx - p * C_;
        int hr = p / HW, hc = p - hr * HW;
        int gy = min(max(y0 - 1 + hr, 0), H_ - 1);
        int gx = min(max(x0 - 1 + hc, 0), W_ - 1);
        sm[OFF_SB + p * 12 + i] = beliefs[((size_t)(b * H_ + gy) * W_ + gx) * C_ + i];
    }
    // constraints tile (float4, coalesced)
    {
        float4* dst = (float4*)&sm[OFF_SC];
        for (int idx = tid; idx < NPIX * 6; idx += NTHREADS) {
            int r = idx / (TW * 6), o = idx - r * (TW * 6);
            const float4* src = (const float4*)(constraints +
                ((size_t)(b * H_ + y0 + r) * W_ + x0) * 24);
            dst[idx] = src[o];
        }
    }
    __syncthreads();

    const int j   = tid & 63;
    const int grp = tid >> 6;   // 0..15

    // ================= Phase B: y = beliefs @ W_neigh over halo =================
    {
        float wn[C_];
        #pragma unroll
        for (int i = 0; i < C_; ++i) wn[i] = sm[OFF_WNEIGH + i * HID_ + j];
        for (int hp = grp; hp < NHALO; hp += 16) {
            const float4 s0 = *(const float4*)&sm[OFF_SB + hp * 12];
            const float4 s1 = *(const float4*)&sm[OFF_SB + hp * 12 + 4];
            const float2 s2 = *(const float2*)&sm[OFF_SB + hp * 12 + 8];
            float y = 0.f;
            y = fmaf(s0.x, wn[0], y); y = fmaf(s0.y, wn[1], y);
            y = fmaf(s0.z, wn[2], y); y = fmaf(s0.w, wn[3], y);
            y = fmaf(s1.x, wn[4], y); y = fmaf(s1.y, wn[5], y);
            y = fmaf(s1.z, wn[6], y); y = fmaf(s1.w, wn[7], y);
            y = fmaf(s2.x, wn[8], y); y = fmaf(s2.y, wn[9], y);
            sm[OFF_SY + hp * HID_ + j] = y;
        }
    }
    __syncthreads();

    // ================= Phase C: hs(p,j) = sum_d relu(a + y_nb + c@wc) =================
    {
        float ws[C_];
        #pragma unroll
        for (int i = 0; i < C_; ++i) ws[i] = sm[OFF_WSELF + i * HID_ + j];
        const float wc0 = sm[OFF_WC + j];
        const float wc1 = sm[OFF_WC + 64 + j];
        const float wc2 = sm[OFF_WC + 128 + j];
        const float bs  = sm[OFF_BASE + j];

        const int row = grp >> 1;            // 0..7
        const int xh  = (grp & 1) * 16;      // x-half: 0 or 16
        const int rt = row * HW, rm = (row + 1) * HW, rb = (row + 2) * HW;

        // sliding 3x3 y-window, init at x = xh
        float yw[9];
        yw[0] = sm[OFF_SY + (rt + xh + 0) * HID_ + j];
        yw[1] = sm[OFF_SY + (rt + xh + 1) * HID_ + j];
        yw[3] = sm[OFF_SY + (rm + xh + 0) * HID_ + j];
        yw[4] = sm[OFF_SY + (rm + xh + 1) * HID_ + j];
        yw[6] = sm[OFF_SY + (rb + xh + 0) * HID_ + j];
        yw[7] = sm[OFF_SY + (rb + xh + 1) * HID_ + j];

        #pragma unroll 1
        for (int xi = 0; xi < 16; ++xi) {
            const int x = xh + xi;
            yw[2] = sm[OFF_SY + (rt + x + 2) * HID_ + j];
            yw[5] = sm[OFF_SY + (rm + x + 2) * HID_ + j];
            yw[8] = sm[OFF_SY + (rb + x + 2) * HID_ + j];

            const int p   = row * TW + x;
            const int hpc = rm + x + 1;

            // a = base + self @ W_self (uniform vec loads)
            const float4 s0 = *(const float4*)&sm[OFF_SB + hpc * 12];
            const float4 s1 = *(const float4*)&sm[OFF_SB + hpc * 12 + 4];
            const float2 s2 = *(const float2*)&sm[OFF_SB + hpc * 12 + 8];
            float a = bs;
            a = fmaf(s0.x, ws[0], a); a = fmaf(s0.y, ws[1], a);
            a = fmaf(s0.z, ws[2], a); a = fmaf(s0.w, ws[3], a);
            a = fmaf(s1.x, ws[4], a); a = fmaf(s1.y, ws[5], a);
            a = fmaf(s1.z, ws[6], a); a = fmaf(s1.w, ws[7], a);
            a = fmaf(s2.x, ws[8], a); a = fmaf(s2.y, ws[9], a);

            const int DI[8] = {0,1,2,3,5,6,7,8};
            const float* cp = &sm[OFF_SC + p * 24];
            float hs = 0.f;
            #pragma unroll
            for (int d = 0; d < 8; ++d) {
                float t = a + yw[DI[d]];
                t = fmaf(cp[3*d+0], wc0, t);
                t = fmaf(cp[3*d+1], wc1, t);
                t = fmaf(cp[3*d+2], wc2, t);
                hs += fmaxf(t, 0.f);
            }
            sm[OFF_SHS + p * HID_ + j] = hs;

            yw[0]=yw[1]; yw[1]=yw[2];
            yw[3]=yw[4]; yw[4]=yw[5];
            yw[6]=yw[7]; yw[7]=yw[8];
        }
    }
    __syncthreads();

    // 8-lane-group mapping for phases D and F
    const int wid  = tid >> 5;   // 0..31
    const int lane = tid & 31;
    const int g    = lane >> 3;
    const int li   = lane & 7;
    const int j0   = li << 3;

    // ================= Phase D: agg = (mean_d relu)@mw2 + mb2 =================
    {
        #pragma unroll 1
        for (int pass = 0; pass < 2; ++pass) {
            const int p = pass * 128 + wid * 4 + g;
            float hs[8];
            *(float4*)&hs[0] = *(const float4*)&sm[OFF_SHS + p * 64 + j0];
            *(float4*)&hs[4] = *(const float4*)&sm[OFF_SHS + p * 64 + j0 + 4];
            float agg[10];
            // two k-chunks of 5: only 5x8 weight regs live at a time
            #pragma unroll
            for (int ch = 0; ch < 2; ++ch) {
                float w2[5][8];
                #pragma unroll
                for (int k = 0; k < 5; ++k) {
                    *(float4*)&w2[k][0] = *(const float4*)&sm[OFF_MW2T + (ch*5+k) * 64 + j0];
                    *(float4*)&w2[k][4] = *(const float4*)&sm[OFF_MW2T + (ch*5+k) * 64 + j0 + 4];
                }
                #pragma unroll
                for (int k = 0; k < 5; ++k) {
                    float s = 0.f;
                    #pragma unroll
                    for (int jj = 0; jj < 8; ++jj) s = fmaf(hs[jj], w2[k][jj], s);
                    agg[ch*5+k] = s;
                }
            }
            #pragma unroll
            for (int o = 1; o < 8; o <<= 1) {
                #pragma unroll
                for (int k = 0; k < 10; ++k)
                    agg[k] += __shfl_xor_sync(0xffffffffu, agg[k], o);
            }
            if (li == 0) {
                #pragma unroll
                for (int k = 0; k < 10; k += 2) {
                    float2 v; v.x = fmaf(agg[k],   0.125f, sm[OFF_MB2 + k]);
                              v.y = fmaf(agg[k+1], 0.125f, sm[OFF_MB2 + k + 1]);
                    *(float2*)&sm[OFF_SAGG + p * 12 + k] = v;
                }
            }
        }
    }
    __syncthreads();

    // ================= Phase E: u = relu([self,agg] @ uw1 + ub1) =================
    {
        float w1[20];      // uw1[:, j] register-resident
        #pragma unroll
        for (int i = 0; i < 20; ++i) w1[i] = sm[OFF_UW1 + i * 64 + j];
        const float b1 = sm[OFF_UB1 + j];

        #pragma unroll 1
        for (int p = grp; p < NPIX; p += 16) {
            const int hpc = ((p >> 5) + 1) * HW + (p & 31) + 1;
            const float4 s0 = *(const float4*)&sm[OFF_SB + hpc * 12];
            const float4 s1 = *(const float4*)&sm[OFF_SB + hpc * 12 + 4];
            const float2 s2 = *(const float2*)&sm[OFF_SB + hpc * 12 + 8];
            const float4 a0 = *(const float4*)&sm[OFF_SAGG + p * 12];
            const float4 a1 = *(const float4*)&sm[OFF_SAGG + p * 12 + 4];
            const float2 a2 = *(const float2*)&sm[OFF_SAGG + p * 12 + 8];
            float u = b1;
            u = fmaf(s0.x, w1[0], u);  u = fmaf(s0.y, w1[1], u);
            u = fmaf(s0.z, w1[2], u);  u = fmaf(s0.w, w1[3], u);
            u = fmaf(s1.x, w1[4], u);  u = fmaf(s1.y, w1[5], u);
            u = fmaf(s1.z, w1[6], u);  u = fmaf(s1.w, w1[7], u);
            u = fmaf(s2.x, w1[8], u);  u = fmaf(s2.y, w1[9], u);
            u = fmaf(a0.x, w1[10], u); u = fmaf(a0.y, w1[11], u);
            u = fmaf(a0.z, w1[12], u); u = fmaf(a0.w, w1[13], u);
            u = fmaf(a1.x, w1[14], u); u = fmaf(a1.y, w1[15], u);
            u = fmaf(a1.z, w1[16], u); u = fmaf(a1.w, w1[17], u);
            u = fmaf(a2.x, w1[18], u); u = fmaf(a2.y, w1[19], u);
            sm[OFF_SU + p * 64 + j] = fmaxf(u, 0.f);
        }
    }
    __syncthreads();

    // ================= Phase F: upd = u @ uw2 + ub2 ; residual + LN =================
    {
        #pragma unroll 1
        for (int pass = 0; pass < 2; ++pass) {
            const int p = pass * 128 + wid * 4 + g;
            float u[8];
            *(float4*)&u[0] = *(const float4*)&sm[OFF_SU + p * 64 + j0];
            *(float4*)&u[4] = *(const float4*)&sm[OFF_SU + p * 64 + j0 + 4];
            float upd[10];
            #pragma unroll
            for (int ch = 0; ch < 2; ++ch) {
                float w2[5][8];
                #pragma unroll
                for (int k = 0; k < 5; ++k) {
                    *(float4*)&w2[k][0] = *(const float4*)&sm[OFF_UW2T + (ch*5+k) * 64 + j0];
                    *(float4*)&w2[k][4] = *(const float4*)&sm[OFF_UW2T + (ch*5+k) * 64 + j0 + 4];
                }
                #pragma unroll
                for (int k = 0; k < 5; ++k) {
                    float s = 0.f;
                    #pragma unroll
                    for (int jj = 0; jj < 8; ++jj) s = fmaf(u[jj], w2[k][jj], s);
                    upd[ch*5+k] = s;
                }
            }
            #pragma unroll
            for (int o = 1; o < 8; o <<= 1) {
                #pragma unroll
                for (int k = 0; k < 10; ++k)
                    upd[k] += __shfl_xor_sync(0xffffffffu, upd[k], o);
            }
            if (li == 0) {
                const int hpc = ((p >> 5) + 1) * HW + (p & 31) + 1;
                const float4 s0 = *(const float4*)&sm[OFF_SB + hpc * 12];
                const float4 s1 = *(const float4*)&sm[OFF_SB + hpc * 12 + 4];
                const float2 s2 = *(const float2*)&sm[OFF_SB + hpc * 12 + 8];
                float sf[10] = {s0.x,s0.y,s0.z,s0.w,s1.x,s1.y,s1.z,s1.w,s2.x,s2.y};
                float x[10]; float mu = 0.f;
                #pragma unroll
                for (int k = 0; k < 10; ++k) {
                    float xv = fmaf(0.5f, upd[k] + sm[OFF_UB2 + k], sf[k]);
                    x[k] = xv; mu += xv;
                }
                mu *= 0.1f;
                float var = 0.f;
                #pragma unroll
                for (int k = 0; k < 10; ++k) { float dk = x[k] - mu; var = fmaf(dk, dk, var); }
                const float inv = rsqrtf(var * 0.1f + 1e-5f);
                #pragma unroll
                for (int k = 0; k < 10; k += 2) {
                    float2 v;
                    v.x = fmaf((x[k]   - mu) * inv, sm[OFF_GAMMA + k],   sm[OFF_BETA + k]);
                    v.y = fmaf((x[k+1] - mu) * inv, sm[OFF_GAMMA + k+1], sm[OFF_BETA + k+1]);
                    *(float2*)&sm[OFF_SOUT + p * C_ + k] = v;
                }
            }
        }
    }
    __syncthreads();

    // ================= Phase G: coalesced float4 store =================
    {
        const float4* src = (const float4*)&sm[OFF_SOUT];
        for (int idx = tid; idx < NPIX * C_ / 4; idx += NTHREADS) {
            int r = idx / 80, o = idx - r * 80;
            float4* dst = (float4*)(out + ((size_t)(b * H_ + y0 + r) * W_ + x0) * C_);
            dst[o] = src[idx];
        }
    }
}

extern "C" void kernel_launch(void* const* d_in, const int* in_sizes, int n_in,
                              void* d_out, int out_size)
{
    const float* beliefs     = (const float*)d_in[0];
    const float* constraints = (const float*)d_in[1];
    const float* fnembed     = (const float*)d_in[2];
    const float* mw1         = (const float*)d_in[3];
    const float* mb1         = (const float*)d_in[4];
    const float* mw2         = (const float*)d_in[5];
    const float* mb2         = (const float*)d_in[6];
    const float* uw1         = (const float*)d_in[7];
    const float* ub1         = (const float*)d_in[8];
    const float* uw2         = (const float*)d_in[9];
    const float* ub2         = (const float*)d_in[10];
    const float* gamma_      = (const float*)d_in[11];
    const float* beta_       = (const float*)d_in[12];
    float* out = (float*)d_out;

    cudaFuncSetAttribute(cmp_kernel, cudaFuncAttributeMaxDynamicSharedMemorySize, SMEM_BYTES);

    dim3 grid(W_ / TW, H_ / TH, B_);
    cmp_kernel<<<grid, NTHREADS, SMEM_BYTES>>>(
        beliefs, constraints, fnembed, mw1, mb1, mw2, mb2,
        uw1, ub1, uw2, ub2, gamma_, beta_, out);
}

// round 6
// speedup vs baseline: 1.1281x; 1.1281x over previous
#include <cuda_runtime.h>
#include <cstdint>

// Problem constants
#define B_  64
#define H_  128
#define W_  128
#define C_  10
#define FD_ 32
#define HID_ 64

// Tile config
#define TW 32
#define TH 8
#define HW 34   // halo width  (TW+2)
#define HH 10   // halo height (TH+2)
#define NPIX  (TW*TH)   // 256
#define NHALO (HW*HH)   // 340
#define NTHREADS 768
#define NGRP 12          // groups of 64 threads

// Shared memory layout (float offsets). Regions reused across phases:
//   SOUT aliases SY  (SY dead after phase C)
//   SAGG aliases SC  (SC dead after phase C)
//   SU   aliases SHS (SHS dead after phase D)
#define OFF_SY     0                          // NHALO*64 = 21760
#define OFF_SOUT   OFF_SY
#define OFF_SB     (OFF_SY + NHALO*HID_)      // rows padded to 12
#define OFF_SC     (OFF_SB + NHALO*12)        // NPIX*24
#define OFF_SAGG   OFF_SC                     // NPIX*12
#define OFF_SHS    (OFF_SC + NPIX*24)         // NPIX*64
#define OFF_SU     OFF_SHS
#define OFF_WSELF  (OFF_SHS + NPIX*HID_)
#define OFF_WNEIGH (OFF_WSELF + 640)
#define OFF_WC     (OFF_WNEIGH + 640)
#define OFF_MW2T   (OFF_WC + 192)
#define OFF_UW2T   (OFF_MW2T + 640)
#define OFF_UW1    (OFF_UW2T + 640)
#define OFF_UB1    (OFF_UW1 + 1280)
#define OFF_BASE   (OFF_UB1 + 64)
#define OFF_MB2    (OFF_BASE + 64)
#define OFF_UB2    (OFF_MB2 + 12)
#define OFF_GAMMA  (OFF_UB2 + 12)
#define OFF_BETA   (OFF_GAMMA + 12)
#define SMEM_FLOATS (OFF_BETA + 12)
#define SMEM_BYTES  (SMEM_FLOATS * 4)         // 210496

__global__ void __launch_bounds__(NTHREADS, 1)
cmp_kernel(const float* __restrict__ beliefs,
           const float* __restrict__ constraints,
           const float* __restrict__ fnembed,
           const float* __restrict__ mw1, const float* __restrict__ mb1,
           const float* __restrict__ mw2, const float* __restrict__ mb2,
           const float* __restrict__ uw1, const float* __restrict__ ub1,
           const float* __restrict__ uw2, const float* __restrict__ ub2,
           const float* __restrict__ gamma_, const float* __restrict__ beta_,
           float* __restrict__ out)
{
    extern __shared__ __align__(16) float sm[];
    const int tid = threadIdx.x;
    const int b  = blockIdx.z;
    const int x0 = blockIdx.x * TW;
    const int y0 = blockIdx.y * TH;

    // ================= Phase A: stage weights + inputs into smem =================
    // mw1 rows: [0,10)=W_self, [10,20)=W_neigh, [20,23)=W_con, [23,55)=W_fn
    for (int i = tid; i < 640; i += NTHREADS) {
        sm[OFF_WSELF  + i] = mw1[i];
        sm[OFF_WNEIGH + i] = mw1[640 + i];
        sm[OFF_MW2T + i] = mw2[(i & 63) * 10 + (i >> 6)];   // [k][j]
        sm[OFF_UW2T + i] = uw2[(i & 63) * 10 + (i >> 6)];
    }
    for (int i = tid; i < 192; i += NTHREADS)  sm[OFF_WC  + i] = mw1[1280 + i];
    for (int i = tid; i < 1280; i += NTHREADS) sm[OFF_UW1 + i] = uw1[i];
    if (tid < 64) {
        sm[OFF_UB1 + tid] = ub1[tid];
        float s = mb1[tid];
        const float* f = fnembed + b * FD_;
        #pragma unroll
        for (int k = 0; k < FD_; ++k)
            s = fmaf(f[k], mw1[(23 + k) * HID_ + tid], s);
        sm[OFF_BASE + tid] = s;
    }
    if (tid >= 64 && tid < 74) {
        int k = tid - 64;
        sm[OFF_MB2   + k] = mb2[k];
        sm[OFF_UB2   + k] = ub2[k];
        sm[OFF_GAMMA + k] = gamma_[k];
        sm[OFF_BETA  + k] = beta_[k];
    }

    // beliefs halo (replicate-pad), rows padded to 12 floats
    for (int idx = tid; idx < NHALO * C_; idx += NTHREADS) {
        int p = idx / C_, i = idx - p * C_;
        int hr = p / HW, hc = p - hr * HW;
        int gy = min(max(y0 - 1 + hr, 0), H_ - 1);
        int gx = min(max(x0 - 1 + hc, 0), W_ - 1);
        sm[OFF_SB + p * 12 + i] = beliefs[((size_t)(b * H_ + gy) * W_ + gx) * C_ + i];
    }
    // constraints tile (float4, coalesced)
    {
        float4* dst = (float4*)&sm[OFF_SC];
        for (int idx = tid; idx < NPIX * 6; idx += NTHREADS) {
            int r = idx / (TW * 6), o = idx - r * (TW * 6);
            const float4* src = (const float4*)(constraints +
                ((size_t)(b * H_ + y0 + r) * W_ + x0) * 24);
            dst[idx] = src[o];
        }
    }
    __syncthreads();

    const int j   = tid & 63;
    const int grp = tid >> 6;   // 0..11

    // ================= Phase B: y = beliefs @ W_neigh over halo =================
    {
        float wn[C_];
        #pragma unroll
        for (int i = 0; i < C_; ++i) wn[i] = sm[OFF_WNEIGH + i * HID_ + j];
        #pragma unroll 1
        for (int hp = grp; hp < NHALO; hp += NGRP) {
            const float4 s0 = *(const float4*)&sm[OFF_SB + hp * 12];
            const float4 s1 = *(const float4*)&sm[OFF_SB + hp * 12 + 4];
            const float2 s2 = *(const float2*)&sm[OFF_SB + hp * 12 + 8];
            float y = 0.f;
            y = fmaf(s0.x, wn[0], y); y = fmaf(s0.y, wn[1], y);
            y = fmaf(s0.z, wn[2], y); y = fmaf(s0.w, wn[3], y);
            y = fmaf(s1.x, wn[4], y); y = fmaf(s1.y, wn[5], y);
            y = fmaf(s1.z, wn[6], y); y = fmaf(s1.w, wn[7], y);
            y = fmaf(s2.x, wn[8], y); y = fmaf(s2.y, wn[9], y);
            sm[OFF_SY + hp * HID_ + j] = y;
        }
    }
    __syncthreads();

    // ================= Phase C: hs(p,j) = sum_d relu(a + y_nb + c@wc) =================
    {
        float ws[C_];
        #pragma unroll
        for (int i = 0; i < C_; ++i) ws[i] = sm[OFF_WSELF + i * HID_ + j];
        const float wc0 = sm[OFF_WC + j];
        const float wc1 = sm[OFF_WC + 64 + j];
        const float wc2 = sm[OFF_WC + 128 + j];
        const float bs  = sm[OFF_BASE + j];

        const int NOFF[8] = {-HW-1, -HW, -HW+1, -1, 1, HW-1, HW, HW+1};

        #pragma unroll 1
        for (int p = grp; p < NPIX; p += NGRP) {
            const int hpc = ((p >> 5) + 1) * HW + (p & 31) + 1;

            // a = base + self @ W_self (uniform vec loads)
            const float4 s0 = *(const float4*)&sm[OFF_SB + hpc * 12];
            const float4 s1 = *(const float4*)&sm[OFF_SB + hpc * 12 + 4];
            const float2 s2 = *(const float2*)&sm[OFF_SB + hpc * 12 + 8];
            float a = bs;
            a = fmaf(s0.x, ws[0], a); a = fmaf(s0.y, ws[1], a);
            a = fmaf(s0.z, ws[2], a); a = fmaf(s0.w, ws[3], a);
            a = fmaf(s1.x, ws[4], a); a = fmaf(s1.y, ws[5], a);
            a = fmaf(s1.z, ws[6], a); a = fmaf(s1.w, ws[7], a);
            a = fmaf(s2.x, ws[8], a); a = fmaf(s2.y, ws[9], a);

            // constraints (uniform vec loads -> short-lived regs)
            float cc[24];
            #pragma unroll
            for (int q = 0; q < 6; ++q) {
                const float4 v = *(const float4*)&sm[OFF_SC + p * 24 + q * 4];
                cc[q*4+0] = v.x; cc[q*4+1] = v.y; cc[q*4+2] = v.z; cc[q*4+3] = v.w;
            }

            float hs = 0.f;
            #pragma unroll
            for (int d = 0; d < 8; ++d) {
                const float yn = sm[OFF_SY + (hpc + NOFF[d]) * HID_ + j];
                float t = a + yn;
                t = fmaf(cc[3*d+0], wc0, t);
                t = fmaf(cc[3*d+1], wc1, t);
                t = fmaf(cc[3*d+2], wc2, t);
                hs += fmaxf(t, 0.f);
            }
            sm[OFF_SHS + p * HID_ + j] = hs;
        }
    }
    __syncthreads();

    // 8-lane-group mapping for phases D and F
    const int wid  = tid >> 5;   // 0..23
    const int lane = tid & 31;
    const int g    = lane >> 3;
    const int li   = lane & 7;
    const int j0   = li << 3;

    // ================= Phase D: agg = (mean_d relu)@mw2 + mb2 =================
    {
        #pragma unroll 1
        for (int pass = 0; pass < 3; ++pass) {
            const int p = pass * 96 + wid * 4 + g;
            if (p >= NPIX) break;   // warp-uniform
            float hs[8];
            *(float4*)&hs[0] = *(const float4*)&sm[OFF_SHS + p * 64 + j0];
            *(float4*)&hs[4] = *(const float4*)&sm[OFF_SHS + p * 64 + j0 + 4];
            float agg[10];
            // two k-chunks of 5: only 5x8 weight regs live at a time
            #pragma unroll
            for (int ch = 0; ch < 2; ++ch) {
                float w2[5][8];
                #pragma unroll
                for (int k = 0; k < 5; ++k) {
                    *(float4*)&w2[k][0] = *(const float4*)&sm[OFF_MW2T + (ch*5+k) * 64 + j0];
                    *(float4*)&w2[k][4] = *(const float4*)&sm[OFF_MW2T + (ch*5+k) * 64 + j0 + 4];
                }
                #pragma unroll
                for (int k = 0; k < 5; ++k) {
                    float s = 0.f;
                    #pragma unroll
                    for (int jj = 0; jj < 8; ++jj) s = fmaf(hs[jj], w2[k][jj], s);
                    agg[ch*5+k] = s;
                }
            }
            #pragma unroll
            for (int o = 1; o < 8; o <<= 1) {
                #pragma unroll
                for (int k = 0; k < 10; ++k)
                    agg[k] += __shfl_xor_sync(0xffffffffu, agg[k], o);
            }
            if (li == 0) {
                #pragma unroll
                for (int k = 0; k < 10; k += 2) {
                    float2 v; v.x = fmaf(agg[k],   0.125f, sm[OFF_MB2 + k]);
                              v.y = fmaf(agg[k+1], 0.125f, sm[OFF_MB2 + k + 1]);
                    *(float2*)&sm[OFF_SAGG + p * 12 + k] = v;
                }
            }
        }
    }
    __syncthreads();

    // ================= Phase E: u = relu([self,agg] @ uw1 + ub1) =================
    {
        float w1[20];      // uw1[:, j] register-resident
        #pragma unroll
        for (int i = 0; i < 20; ++i) w1[i] = sm[OFF_UW1 + i * 64 + j];
        const float b1 = sm[OFF_UB1 + j];

        #pragma unroll 1
        for (int p = grp; p < NPIX; p += NGRP) {
            const int hpc = ((p >> 5) + 1) * HW + (p & 31) + 1;
            const float4 s0 = *(const float4*)&sm[OFF_SB + hpc * 12];
            const float4 s1 = *(const float4*)&sm[OFF_SB + hpc * 12 + 4];
            const float2 s2 = *(const float2*)&sm[OFF_SB + hpc * 12 + 8];
            const float4 a0 = *(const float4*)&sm[OFF_SAGG + p * 12];
            const float4 a1 = *(const float4*)&sm[OFF_SAGG + p * 12 + 4];
            const float2 a2 = *(const float2*)&sm[OFF_SAGG + p * 12 + 8];
            float u = b1;
            u = fmaf(s0.x, w1[0], u);  u = fmaf(s0.y, w1[1], u);
            u = fmaf(s0.z, w1[2], u);  u = fmaf(s0.w, w1[3], u);
            u = fmaf(s1.x, w1[4], u);  u = fmaf(s1.y, w1[5], u);
            u = fmaf(s1.z, w1[6], u);  u = fmaf(s1.w, w1[7], u);
            u = fmaf(s2.x, w1[8], u);  u = fmaf(s2.y, w1[9], u);
            u = fmaf(a0.x, w1[10], u); u = fmaf(a0.y, w1[11], u);
            u = fmaf(a0.z, w1[12], u); u = fmaf(a0.w, w1[13], u);
            u = fmaf(a1.x, w1[14], u); u = fmaf(a1.y, w1[15], u);
            u = fmaf(a1.z, w1[16], u); u = fmaf(a1.w, w1[17], u);
            u = fmaf(a2.x, w1[18], u); u = fmaf(a2.y, w1[19], u);
            sm[OFF_SU + p * 64 + j] = fmaxf(u, 0.f);
        }
    }
    __syncthreads();

    // ================= Phase F: upd = u @ uw2 + ub2 ; residual + LN =================
    {
        #pragma unroll 1
        for (int pass = 0; pass < 3; ++pass) {
            const int p = pass * 96 + wid * 4 + g;
            if (p >= NPIX) break;   // warp-uniform
            float u[8];
            *(float4*)&u[0] = *(const float4*)&sm[OFF_SU + p * 64 + j0];
            *(float4*)&u[4] = *(const float4*)&sm[OFF_SU + p * 64 + j0 + 4];
            float upd[10];
            #pragma unroll
            for (int ch = 0; ch < 2; ++ch) {
                float w2[5][8];
                #pragma unroll
                for (int k = 0; k < 5; ++k) {
                    *(float4*)&w2[k][0] = *(const float4*)&sm[OFF_UW2T + (ch*5+k) * 64 + j0];
                    *(float4*)&w2[k][4] = *(const float4*)&sm[OFF_UW2T + (ch*5+k) * 64 + j0 + 4];
                }
                #pragma unroll
                for (int k = 0; k < 5; ++k) {
                    float s = 0.f;
                    #pragma unroll
                    for (int jj = 0; jj < 8; ++jj) s = fmaf(u[jj], w2[k][jj], s);
                    upd[ch*5+k] = s;
                }
            }
            #pragma unroll
            for (int o = 1; o < 8; o <<= 1) {
                #pragma unroll
                for (int k = 0; k < 10; ++k)
                    upd[k] += __shfl_xor_sync(0xffffffffu, upd[k], o);
            }
            if (li == 0) {
                const int hpc = ((p >> 5) + 1) * HW + (p & 31) + 1;
                const float4 s0 = *(const float4*)&sm[OFF_SB + hpc * 12];
                const float4 s1 = *(const float4*)&sm[OFF_SB + hpc * 12 + 4];
                const float2 s2 = *(const float2*)&sm[OFF_SB + hpc * 12 + 8];
                float sf[10] = {s0.x,s0.y,s0.z,s0.w,s1.x,s1.y,s1.z,s1.w,s2.x,s2.y};
                float x[10]; float mu = 0.f;
                #pragma unroll
                for (int k = 0; k < 10; ++k) {
                    float xv = fmaf(0.5f, upd[k] + sm[OFF_UB2 + k], sf[k]);
                    x[k] = xv; mu += xv;
                }
                mu *= 0.1f;
                float var = 0.f;
                #pragma unroll
                for (int k = 0; k < 10; ++k) { float dk = x[k] - mu; var = fmaf(dk, dk, var); }
                const float inv = rsqrtf(var * 0.1f + 1e-5f);
                #pragma unroll
                for (int k = 0; k < 10; k += 2) {
                    float2 v;
                    v.x = fmaf((x[k]   - mu) * inv, sm[OFF_GAMMA + k],   sm[OFF_BETA + k]);
                    v.y = fmaf((x[k+1] - mu) * inv, sm[OFF_GAMMA + k+1], sm[OFF_BETA + k+1]);
                    *(float2*)&sm[OFF_SOUT + p * C_ + k] = v;
                }
            }
        }
    }
    __syncthreads();

    // ================= Phase G: coalesced float4 store =================
    {
        const float4* src = (const float4*)&sm[OFF_SOUT];
        for (int idx = tid; idx < NPIX * C_ / 4; idx += NTHREADS) {
            int r = idx / 80, o = idx - r * 80;
            float4* dst = (float4*)(out + ((size_t)(b * H_ + y0 + r) * W_ + x0) * C_);
            dst[o] = src[idx];
        }
    }
}

extern "C" void kernel_launch(void* const* d_in, const int* in_sizes, int n_in,
                              void* d_out, int out_size)
{
    const float* beliefs     = (const float*)d_in[0];
    const float* constraints = (const float*)d_in[1];
    const float* fnembed     = (const float*)d_in[2];
    const float* mw1         = (const float*)d_in[3];
    const float* mb1         = (const float*)d_in[4];
    const float* mw2         = (const float*)d_in[5];
    const float* mb2         = (const float*)d_in[6];
    const float* uw1         = (const float*)d_in[7];
    const float* ub1         = (const float*)d_in[8];
    const float* uw2         = (const float*)d_in[9];
    const float* ub2         = (const float*)d_in[10];
    const float* gamma_      = (const float*)d_in[11];
    const float* beta_       = (const float*)d_in[12];
    float* out = (float*)d_out;

    cudaFuncSetAttribute(cmp_kernel, cudaFuncAttributeMaxDynamicSharedMemorySize, SMEM_BYTES);

    dim3 grid(W_ / TW, H_ / TH, B_);
    cmp_kernel<<<grid, NTHREADS, SMEM_BYTES>>>(
        beliefs, constraints, fnembed, mw1, mb1, mw2, mb2,
        uw1, ub1, uw2, ub2, gamma_, beta_, out);
}

// round 7
// speedup vs baseline: 1.5379x; 1.3633x over previous
#include <cuda_runtime.h>
#include <cstdint>

// Problem constants
#define B_  64
#define H_  128
#define W_  128
#define C_  10
#define FD_ 32
#define HID_ 64

// Tile config
#define TW 32
#define TH 8
#define HW 34   // halo width  (TW+2)
#define HH 10   // halo height (TH+2)
#define NPIX  (TW*TH)   // 256
#define NHALO (HW*HH)   // 340
#define NTHREADS 512
#define NWARP 16

// Hidden-dim "pos" layout: pos(j) = 2*(j&31) + (j>>5); j(pos) = (pos>>1) + (pos&1)*32
// y / hs / u arrays and all per-j weights are stored in pos order, so a warp
// lane owns the pair (j=lane, j=lane+32) as one float2 at offset 2*lane.

// Shared memory layout (float offsets). Regions reused across phases:
//   SOUT aliases SY  (SY dead after phase C)
//   SAGG aliases SC  (SC dead after phase C)
//   SU   aliases SHS (SHS dead after phase D)
#define OFF_SY     0                          // NHALO*64 = 21760
#define OFF_SOUT   OFF_SY
#define OFF_SB     (OFF_SY + NHALO*HID_)      // rows padded to 12
#define OFF_SC     (OFF_SB + NHALO*12)        // NPIX*24
#define OFF_SAGG   OFF_SC                     // NPIX*12
#define OFF_SHS    (OFF_SC + NPIX*24)        // NPIX*64
#define OFF_SU     OFF_SHS
#define OFF_WSELF  (OFF_SHS + NPIX*HID_)      // pos-interleaved
#define OFF_WNEIGH (OFF_WSELF + 640)          // pos-interleaved
#define OFF_WC     (OFF_WNEIGH + 640)         // pos-interleaved
#define OFF_MW2T   (OFF_WC + 192)             // [k][pos]
#define OFF_UW2T   (OFF_MW2T + 640)           // [k][pos]
#define OFF_UW1    (OFF_UW2T + 640)           // pos-interleaved
#define OFF_UB1    (OFF_UW1 + 1280)           // pos-interleaved
#define OFF_BASE   (OFF_UB1 + 64)             // pos-interleaved
#define OFF_MB2    (OFF_BASE + 64)
#define OFF_UB2    (OFF_MB2 + 12)
#define OFF_GAMMA  (OFF_UB2 + 12)
#define OFF_BETA   (OFF_GAMMA + 12)
#define SMEM_FLOATS (OFF_BETA + 12)
#define SMEM_BYTES  (SMEM_FLOATS * 4)         // 210496

__global__ void __launch_bounds__(NTHREADS, 1)
cmp_kernel(const float* __restrict__ beliefs,
           const float* __restrict__ constraints,
           const float* __restrict__ fnembed,
           const float* __restrict__ mw1, const float* __restrict__ mb1,
           const float* __restrict__ mw2, const float* __restrict__ mb2,
           const float* __restrict__ uw1, const float* __restrict__ ub1,
           const float* __restrict__ uw2, const float* __restrict__ ub2,
           const float* __restrict__ gamma_, const float* __restrict__ beta_,
           float* __restrict__ out)
{
    extern __shared__ __align__(16) float sm[];
    const int tid = threadIdx.x;
    const int b  = blockIdx.z;
    const int x0 = blockIdx.x * TW;
    const int y0 = blockIdx.y * TH;

    // ================= Phase A: stage weights + inputs into smem =================
    // mw1 rows: [0,10)=W_self, [10,20)=W_neigh, [20,23)=W_con, [23,55)=W_fn
    // Per-j arrays stored pos-interleaved: dst[row*64 + pos] = src[row*64 + j(pos)]
    for (int i = tid; i < 640; i += NTHREADS) {
        const int row = i >> 6, pos = i & 63;
        const int jj = (pos >> 1) + ((pos & 1) << 5);
        sm[OFF_WSELF  + i] = mw1[row * 64 + jj];
        sm[OFF_WNEIGH + i] = mw1[640 + row * 64 + jj];
        sm[OFF_MW2T + i] = mw2[jj * 10 + row];   // [k][pos], k=row? no: row in 0..9? 640/64=10 rows ✓
        sm[OFF_UW2T + i] = uw2[jj * 10 + row];
    }
    for (int i = tid; i < 192; i += NTHREADS) {
        const int row = i >> 6, pos = i & 63;
        const int jj = (pos >> 1) + ((pos & 1) << 5);
        sm[OFF_WC + i] = mw1[1280 + row * 64 + jj];
    }
    for (int i = tid; i < 1280; i += NTHREADS) {
        const int row = i >> 6, pos = i & 63;
        const int jj = (pos >> 1) + ((pos & 1) << 5);
        sm[OFF_UW1 + i] = uw1[row * 64 + jj];
    }
    if (tid < 64) {
        const int pos = 2 * (tid & 31) + (tid >> 5);   // pos(j=tid)
        sm[OFF_UB1 + pos] = ub1[tid];
        float s = mb1[tid];
        const float* f = fnembed + b * FD_;
        #pragma unroll
        for (int k = 0; k < FD_; ++k)
            s = fmaf(f[k], mw1[(23 + k) * HID_ + tid], s);
        sm[OFF_BASE + pos] = s;
    }
    if (tid >= 64 && tid < 74) {
        int k = tid - 64;
        sm[OFF_MB2   + k] = mb2[k];
        sm[OFF_UB2   + k] = ub2[k];
        sm[OFF_GAMMA + k] = gamma_[k];
        sm[OFF_BETA  + k] = beta_[k];
    }

    // beliefs halo (replicate-pad), rows padded to 12 floats
    for (int idx = tid; idx < NHALO * C_; idx += NTHREADS) {
        int p = idx / C_, i = idx - p * C_;
        int hr = p / HW, hc = p - hr * HW;
        int gy = min(max(y0 - 1 + hr, 0), H_ - 1);
        int gx = min(max(x0 - 1 + hc, 0), W_ - 1);
        sm[OFF_SB + p * 12 + i] = beliefs[((size_t)(b * H_ + gy) * W_ + gx) * C_ + i];
    }
    // constraints tile (float4, coalesced)
    {
        float4* dst = (float4*)&sm[OFF_SC];
        for (int idx = tid; idx < NPIX * 6; idx += NTHREADS) {
            int r = idx / (TW * 6), o = idx - r * (TW * 6);
            const float4* src = (const float4*)(constraints +
                ((size_t)(b * H_ + y0 + r) * W_ + x0) * 24);
            dst[idx] = src[o];
        }
    }
    __syncthreads();

    const int lane = tid & 31;
    const int wrp  = tid >> 5;   // 0..15
    const int pp   = 2 * lane;   // float2 offset for this thread's (j, j+32) pair

    // ================= Phase B: y = beliefs @ W_neigh over halo (1 warp/pixel) ====
    {
        float2 wn[C_];
        #pragma unroll
        for (int i = 0; i < C_; ++i) wn[i] = *(const float2*)&sm[OFF_WNEIGH + i * 64 + pp];
        #pragma unroll 1
        for (int hp = wrp; hp < NHALO; hp += NWARP) {
            const float4 s0 = *(const float4*)&sm[OFF_SB + hp * 12];
            const float4 s1 = *(const float4*)&sm[OFF_SB + hp * 12 + 4];
            const float2 s2 = *(const float2*)&sm[OFF_SB + hp * 12 + 8];
            float yx = 0.f, yy = 0.f;
            yx = fmaf(s0.x, wn[0].x, yx); yy = fmaf(s0.x, wn[0].y, yy);
            yx = fmaf(s0.y, wn[1].x, yx); yy = fmaf(s0.y, wn[1].y, yy);
            yx = fmaf(s0.z, wn[2].x, yx); yy = fmaf(s0.z, wn[2].y, yy);
            yx = fmaf(s0.w, wn[3].x, yx); yy = fmaf(s0.w, wn[3].y, yy);
            yx = fmaf(s1.x, wn[4].x, yx); yy = fmaf(s1.x, wn[4].y, yy);
            yx = fmaf(s1.y, wn[5].x, yx); yy = fmaf(s1.y, wn[5].y, yy);
            yx = fmaf(s1.z, wn[6].x, yx); yy = fmaf(s1.z, wn[6].y, yy);
            yx = fmaf(s1.w, wn[7].x, yx); yy = fmaf(s1.w, wn[7].y, yy);
            yx = fmaf(s2.x, wn[8].x, yx); yy = fmaf(s2.x, wn[8].y, yy);
            yx = fmaf(s2.y, wn[9].x, yx); yy = fmaf(s2.y, wn[9].y, yy);
            float2 y; y.x = yx; y.y = yy;
            *(float2*)&sm[OFF_SY + hp * HID_ + pp] = y;
        }
    }
    __syncthreads();

    // ================= Phase C: hs = sum_d relu(a + y_nb + c@wc), sliding window ==
    {
        float2 ws[C_];
        #pragma unroll
        for (int i = 0; i < C_; ++i) ws[i] = *(const float2*)&sm[OFF_WSELF + i * 64 + pp];
        const float2 wc0 = *(const float2*)&sm[OFF_WC + pp];
        const float2 wc1 = *(const float2*)&sm[OFF_WC + 64 + pp];
        const float2 wc2 = *(const float2*)&sm[OFF_WC + 128 + pp];
        const float2 bs  = *(const float2*)&sm[OFF_BASE + pp];

        const int row = wrp >> 1;            // 0..7
        const int xh  = (wrp & 1) * 16;      // x-half: 0 or 16
        const int rt = row * HW, rm = (row + 1) * HW, rb = (row + 2) * HW;

        // sliding 3x3 y-window (center slot 4 carried, unused)
        float2 yw[9];
        yw[0] = *(const float2*)&sm[OFF_SY + (rt + xh + 0) * HID_ + pp];
        yw[1] = *(const float2*)&sm[OFF_SY + (rt + xh + 1) * HID_ + pp];
        yw[3] = *(const float2*)&sm[OFF_SY + (rm + xh + 0) * HID_ + pp];
        yw[4] = *(const float2*)&sm[OFF_SY + (rm + xh + 1) * HID_ + pp];
        yw[6] = *(const float2*)&sm[OFF_SY + (rb + xh + 0) * HID_ + pp];
        yw[7] = *(const float2*)&sm[OFF_SY + (rb + xh + 1) * HID_ + pp];

        #pragma unroll 1
        for (int xi = 0; xi < 16; ++xi) {
            const int x = xh + xi;
            yw[2] = *(const float2*)&sm[OFF_SY + (rt + x + 2) * HID_ + pp];
            yw[5] = *(const float2*)&sm[OFF_SY + (rm + x + 2) * HID_ + pp];
            yw[8] = *(const float2*)&sm[OFF_SY + (rb + x + 2) * HID_ + pp];

            const int p   = row * TW + x;
            const int hpc = rm + x + 1;

            // a = base + self @ W_self (uniform vec loads)
            const float4 s0 = *(const float4*)&sm[OFF_SB + hpc * 12];
            const float4 s1 = *(const float4*)&sm[OFF_SB + hpc * 12 + 4];
            const float2 s2 = *(const float2*)&sm[OFF_SB + hpc * 12 + 8];
            float ax = bs.x, ay = bs.y;
            ax = fmaf(s0.x, ws[0].x, ax); ay = fmaf(s0.x, ws[0].y, ay);
            ax = fmaf(s0.y, ws[1].x, ax); ay = fmaf(s0.y, ws[1].y, ay);
            ax = fmaf(s0.z, ws[2].x, ax); ay = fmaf(s0.z, ws[2].y, ay);
            ax = fmaf(s0.w, ws[3].x, ax); ay = fmaf(s0.w, ws[3].y, ay);
            ax = fmaf(s1.x, ws[4].x, ax); ay = fmaf(s1.x, ws[4].y, ay);
            ax = fmaf(s1.y, ws[5].x, ax); ay = fmaf(s1.y, ws[5].y, ay);
            ax = fmaf(s1.z, ws[6].x, ax); ay = fmaf(s1.z, ws[6].y, ay);
            ax = fmaf(s1.w, ws[7].x, ax); ay = fmaf(s1.w, ws[7].y, ay);
            ax = fmaf(s2.x, ws[8].x, ax); ay = fmaf(s2.x, ws[8].y, ay);
            ax = fmaf(s2.y, ws[9].x, ax); ay = fmaf(s2.y, ws[9].y, ay);

            // constraints (uniform vec loads, issued once per warp now)
            float cc[24];
            #pragma unroll
            for (int q = 0; q < 6; ++q) {
                const float4 v = *(const float4*)&sm[OFF_SC + p * 24 + q * 4];
                cc[q*4+0] = v.x; cc[q*4+1] = v.y; cc[q*4+2] = v.z; cc[q*4+3] = v.w;
            }

            const int DI[8] = {0,1,2,3,5,6,7,8};
            float hx = 0.f, hy = 0.f;
            #pragma unroll
            for (int d = 0; d < 8; ++d) {
                const float2 yn = yw[DI[d]];
                float tx = ax + yn.x;
                float ty = ay + yn.y;
                tx = fmaf(cc[3*d+0], wc0.x, tx); ty = fmaf(cc[3*d+0], wc0.y, ty);
                tx = fmaf(cc[3*d+1], wc1.x, tx); ty = fmaf(cc[3*d+1], wc1.y, ty);
                tx = fmaf(cc[3*d+2], wc2.x, tx); ty = fmaf(cc[3*d+2], wc2.y, ty);
                hx += fmaxf(tx, 0.f);
                hy += fmaxf(ty, 0.f);
            }
            float2 hs; hs.x = hx; hs.y = hy;
            *(float2*)&sm[OFF_SHS + p * HID_ + pp] = hs;

            yw[0]=yw[1]; yw[1]=yw[2];
            yw[3]=yw[4]; yw[4]=yw[5];
            yw[6]=yw[7]; yw[7]=yw[8];
        }
    }
    __syncthreads();

    // 8-lane-group mapping for phases D and F (pos-order, consistent with MW2T/UW2T)
    const int g    = lane >> 3;
    const int li   = lane & 7;
    const int j0   = li << 3;

    // ================= Phase D: agg = (mean_d relu)@mw2 + mb2 =================
    {
        float w2[10][8];   // register-resident across all passes
        #pragma unroll
        for (int k = 0; k < 10; ++k) {
            *(float4*)&w2[k][0] = *(const float4*)&sm[OFF_MW2T + k * 64 + j0];
            *(float4*)&w2[k][4] = *(const float4*)&sm[OFF_MW2T + k * 64 + j0 + 4];
        }
        float mb2r[10];
        #pragma unroll
        for (int k = 0; k < 10; ++k) mb2r[k] = sm[OFF_MB2 + k];

        #pragma unroll 1
        for (int pass = 0; pass < 4; ++pass) {
            const int p = pass * 64 + wrp * 4 + g;
            float hs[8];
            *(float4*)&hs[0] = *(const float4*)&sm[OFF_SHS + p * 64 + j0];
            *(float4*)&hs[4] = *(const float4*)&sm[OFF_SHS + p * 64 + j0 + 4];
            float agg[10];
            #pragma unroll
            for (int k = 0; k < 10; ++k) {
                float s = 0.f;
                #pragma unroll
                for (int jj = 0; jj < 8; ++jj) s = fmaf(hs[jj], w2[k][jj], s);
                agg[k] = s;
            }
            #pragma unroll
            for (int o = 1; o < 8; o <<= 1) {
                #pragma unroll
                for (int k = 0; k < 10; ++k)
                    agg[k] += __shfl_xor_sync(0xffffffffu, agg[k], o);
            }
            if (li == 0) {
                #pragma unroll
                for (int k = 0; k < 10; k += 2) {
                    float2 v; v.x = fmaf(agg[k],   0.125f, mb2r[k]);
                              v.y = fmaf(agg[k+1], 0.125f, mb2r[k+1]);
                    *(float2*)&sm[OFF_SAGG + p * 12 + k] = v;
                }
            }
        }
    }
    __syncthreads();

    // ================= Phase E: u = relu([self,agg] @ uw1 + ub1) =================
    {
        float2 w1[20];     // uw1[:, pair] register-resident (40 regs)
        #pragma unroll
        for (int i = 0; i < 20; ++i) w1[i] = *(const float2*)&sm[OFF_UW1 + i * 64 + pp];
        const float2 b1 = *(const float2*)&sm[OFF_UB1 + pp];

        #pragma unroll 1
        for (int p = wrp; p < NPIX; p += NWARP) {
            const int hpc = ((p >> 5) + 1) * HW + (p & 31) + 1;
            const float4 s0 = *(const float4*)&sm[OFF_SB + hpc * 12];
            const float4 s1 = *(const float4*)&sm[OFF_SB + hpc * 12 + 4];
            const float2 s2 = *(const float2*)&sm[OFF_SB + hpc * 12 + 8];
            const float4 a0 = *(const float4*)&sm[OFF_SAGG + p * 12];
            const float4 a1 = *(const float4*)&sm[OFF_SAGG + p * 12 + 4];
            const float2 a2 = *(const float2*)&sm[OFF_SAGG + p * 12 + 8];
            float ux = b1.x, uy = b1.y;
            ux = fmaf(s0.x, w1[0].x,  ux); uy = fmaf(s0.x, w1[0].y,  uy);
            ux = fmaf(s0.y, w1[1].x,  ux); uy = fmaf(s0.y, w1[1].y,  uy);
            ux = fmaf(s0.z, w1[2].x,  ux); uy = fmaf(s0.z, w1[2].y,  uy);
            ux = fmaf(s0.w, w1[3].x,  ux); uy = fmaf(s0.w, w1[3].y,  uy);
            ux = fmaf(s1.x, w1[4].x,  ux); uy = fmaf(s1.x, w1[4].y,  uy);
            ux = fmaf(s1.y, w1[5].x,  ux); uy = fmaf(s1.y, w1[5].y,  uy);
            ux = fmaf(s1.z, w1[6].x,  ux); uy = fmaf(s1.z, w1[6].y,  uy);
            ux = fmaf(s1.w, w1[7].x,  ux); uy = fmaf(s1.w, w1[7].y,  uy);
            ux = fmaf(s2.x, w1[8].x,  ux); uy = fmaf(s2.x, w1[8].y,  uy);
            ux = fmaf(s2.y, w1[9].x,  ux); uy = fmaf(s2.y, w1[9].y,  uy);
            ux = fmaf(a0.x, w1[10].x, ux); uy = fmaf(a0.x, w1[10].y, uy);
            ux = fmaf(a0.y, w1[11].x, ux); uy = fmaf(a0.y, w1[11].y, uy);
            ux = fmaf(a0.z, w1[12].x, ux); uy = fmaf(a0.z, w1[12].y, uy);
            ux = fmaf(a0.w, w1[13].x, ux); uy = fmaf(a0.w, w1[13].y, uy);
            ux = fmaf(a1.x, w1[14].x, ux); uy = fmaf(a1.x, w1[14].y, uy);
            ux = fmaf(a1.y, w1[15].x, ux); uy = fmaf(a1.y, w1[15].y, uy);
            ux = fmaf(a1.z, w1[16].x, ux); uy = fmaf(a1.z, w1[16].y, uy);
            ux = fmaf(a1.w, w1[17].x, ux); uy = fmaf(a1.w, w1[17].y, uy);
            ux = fmaf(a2.x, w1[18].x, ux); uy = fmaf(a2.x, w1[18].y, uy);
            ux = fmaf(a2.y, w1[19].x, ux); uy = fmaf(a2.y, w1[19].y, uy);
            float2 u; u.x = fmaxf(ux, 0.f); u.y = fmaxf(uy, 0.f);
            *(float2*)&sm[OFF_SU + p * 64 + pp] = u;
        }
    }
    __syncthreads();

    // ================= Phase F: upd = u @ uw2 + ub2 ; residual + LN =================
    {
        float w2[10][8];   // uw2t register-resident
        #pragma unroll
        for (int k = 0; k < 10; ++k) {
            *(float4*)&w2[k][0] = *(const float4*)&sm[OFF_UW2T + k * 64 + j0];
            *(float4*)&w2[k][4] = *(const float4*)&sm[OFF_UW2T + k * 64 + j0 + 4];
        }

        #pragma unroll 1
        for (int pass = 0; pass < 4; ++pass) {
            const int p = pass * 64 + wrp * 4 + g;
            float u[8];
            *(float4*)&u[0] = *(const float4*)&sm[OFF_SU + p * 64 + j0];
            *(float4*)&u[4] = *(const float4*)&sm[OFF_SU + p * 64 + j0 + 4];
            float upd[10];
            #pragma unroll
            for (int k = 0; k < 10; ++k) {
                float s = 0.f;
                #pragma unroll
                for (int jj = 0; jj < 8; ++jj) s = fmaf(u[jj], w2[k][jj], s);
                upd[k] = s;
            }
            #pragma unroll
            for (int o = 1; o < 8; o <<= 1) {
                #pragma unroll
                for (int k = 0; k < 10; ++k)
                    upd[k] += __shfl_xor_sync(0xffffffffu, upd[k], o);
            }
            if (li == 0) {
                const int hpc = ((p >> 5) + 1) * HW + (p & 31) + 1;
                const float4 s0 = *(const float4*)&sm[OFF_SB + hpc * 12];
                const float4 s1 = *(const float4*)&sm[OFF_SB + hpc * 12 + 4];
                const float2 s2 = *(const float2*)&sm[OFF_SB + hpc * 12 + 8];
                float sf[10] = {s0.x,s0.y,s0.z,s0.w,s1.x,s1.y,s1.z,s1.w,s2.x,s2.y};
                float x[10]; float mu = 0.f;
                #pragma unroll
                for (int k = 0; k < 10; ++k) {
                    float xv = fmaf(0.5f, upd[k] + sm[OFF_UB2 + k], sf[k]);
                    x[k] = xv; mu += xv;
                }
                mu *= 0.1f;
                float var = 0.f;
                #pragma unroll
                for (int k = 0; k < 10; ++k) { float dk = x[k] - mu; var = fmaf(dk, dk, var); }
                const float inv = rsqrtf(var * 0.1f + 1e-5f);
                #pragma unroll
                for (int k = 0; k < 10; k += 2) {
                    float2 v;
                    v.x = fmaf((x[k]   - mu) * inv, sm[OFF_GAMMA + k],   sm[OFF_BETA + k]);
                    v.y = fmaf((x[k+1] - mu) * inv, sm[OFF_GAMMA + k+1], sm[OFF_BETA + k+1]);
                    *(float2*)&sm[OFF_SOUT + p * C_ + k] = v;
                }
            }
        }
    }
    __syncthreads();

    // ================= Phase G: coalesced float4 store =================
    {
        const float4* src = (const float4*)&sm[OFF_SOUT];
        for (int idx = tid; idx < NPIX * C_ / 4; idx += NTHREADS) {
            int r = idx / 80, o = idx - r * 80;
            float4* dst = (float4*)(out + ((size_t)(b * H_ + y0 + r) * W_ + x0) * C_);
            dst[o] = src[idx];
        }
    }
}

extern "C" void kernel_launch(void* const* d_in, const int* in_sizes, int n_in,
                              void* d_out, int out_size)
{
    const float* beliefs     = (const float*)d_in[0];
    const float* constraints = (const float*)d_in[1];
    const float* fnembed     = (const float*)d_in[2];
    const float* mw1         = (const float*)d_in[3];
    const float* mb1         = (const float*)d_in[4];
    const float* mw2         = (const float*)d_in[5];
    const float* mb2         = (const float*)d_in[6];
    const float* uw1         = (const float*)d_in[7];
    const float* ub1         = (const float*)d_in[8];
    const float* uw2         = (const float*)d_in[9];
    const float* ub2         = (const float*)d_in[10];
    const float* gamma_      = (const float*)d_in[11];
    const float* beta_       = (const float*)d_in[12];
    float* out = (float*)d_out;

    cudaFuncSetAttribute(cmp_kernel, cudaFuncAttributeMaxDynamicSharedMemorySize, SMEM_BYTES);

    dim3 grid(W_ / TW, H_ / TH, B_);
    cmp_kernel<<<grid, NTHREADS, SMEM_BYTES>>>(
        beliefs, constraints, fnembed, mw1, mb1, mw2, mb2,
        uw1, ub1, uw2, ub2, gamma_, beta_, out);
}